// round 17
// baseline (speedup 1.0000x reference)
#include <cuda_runtime.h>
#include <cuda_fp16.h>
#include <cstdint>

// Varlen causal GQA flash attention — round 17 (= R16 + st.shared fix).
// Cooperative warp pairs cut smem-crossbar traffic ~30%:
//  4 row-groups x 32 rows; pair (w, w+4) [same SMSP] splits QK by token-half
//  (K reads halved) and PV by dim-half (V reads halved); P exchanged through
//  a smem buffer (written with st.shared.b32 — shared-window addresses must
//  not be dereferenced as generic pointers, the R16 bug). 2-stage cp.async ring.

#define TQ 128
#define TKS 128
#define TK 64
#define DH 128
#define NT 256
#define QSTRIDE 4096
#define KSTRIDE 1024
#define PADH 136
#define PPADH 136

#define K_ST_HALVES (TKS * PADH)          // 17408
#define STAGE_HALVES (2 * K_ST_HALVES)
#define STAGE_BYTES (STAGE_HALVES * 2)    // 69632
#define P_OFF_B (2 * STAGE_BYTES)         // 139264
#define L_OFF_B (P_OFF_B + 128 * PPADH * 2)  // 174080
#define SMEM_BYTES (L_OFF_B + 1024)       // 175104

#define CAP_TOK 8192
__device__ __half g_kh[CAP_TOK * KSTRIDE];
__device__ __half g_vh[CAP_TOK * KSTRIDE];

static __device__ __forceinline__ uint32_t smem_u32(const void* p) {
    uint32_t a;
    asm("{ .reg .u64 t; cvta.to.shared.u64 t, %1; cvt.u32.u64 %0, t; }" : "=r"(a) : "l"(p));
    return a;
}
static __device__ __forceinline__ uint32_t pack_h2(float lo, float hi) {
    uint32_t u;
    asm("cvt.rn.f16x2.f32 %0, %1, %2;" : "=r"(u) : "f"(hi), "f"(lo));
    return u;
}
static __device__ __forceinline__ float exp2f_fast(float x) {
    float y; asm("ex2.approx.ftz.f32 %0, %1;" : "=f"(y) : "f"(x)); return y;
}
static __device__ __forceinline__ void sts32(uint32_t addr, uint32_t v) {
    asm volatile("st.shared.b32 [%0], %1;" :: "r"(addr), "r"(v) : "memory");
}
static __device__ __forceinline__ void mma_f16(float c[4], const uint32_t a[4],
                                               uint32_t b0, uint32_t b1) {
    asm("mma.sync.aligned.m16n8k16.row.col.f32.f16.f16.f32 "
        "{%0,%1,%2,%3}, {%4,%5,%6,%7}, {%8,%9}, {%0,%1,%2,%3};"
        : "+f"(c[0]), "+f"(c[1]), "+f"(c[2]), "+f"(c[3])
        : "r"(a[0]), "r"(a[1]), "r"(a[2]), "r"(a[3]), "r"(b0), "r"(b1));
}
static __device__ __forceinline__ void ldsm4(uint32_t r[4], uint32_t addr) {
    asm volatile("ldmatrix.sync.aligned.m8n8.x4.shared.b16 {%0,%1,%2,%3}, [%4];"
        : "=r"(r[0]), "=r"(r[1]), "=r"(r[2]), "=r"(r[3]) : "r"(addr));
}
static __device__ __forceinline__ void ldsm4t(uint32_t r[4], uint32_t addr) {
    asm volatile("ldmatrix.sync.aligned.m8n8.x4.trans.shared.b16 {%0,%1,%2,%3}, [%4];"
        : "=r"(r[0]), "=r"(r[1]), "=r"(r[2]), "=r"(r[3]) : "r"(addr));
}
static __device__ __forceinline__ void cp16(uint32_t dst, const void* src, uint32_t n) {
    asm volatile("cp.async.cg.shared.global [%0], [%1], 16, %2;"
        :: "r"(dst), "l"(src), "r"(n) : "memory");
}
static __device__ __forceinline__ void cp_commit() {
    asm volatile("cp.async.commit_group;" ::: "memory");
}
static __device__ __forceinline__ void cp_wait0() {
    asm volatile("cp.async.wait_group 0;" ::: "memory");
}

// ---------------- pre-pass: fp32 K/V -> fp16 scratch ----------------
__global__ void cvt_kv_kernel(const float* __restrict__ k, const float* __restrict__ v,
                              int n8)
{
    for (int i = blockIdx.x * blockDim.x + threadIdx.x; i < n8;
         i += gridDim.x * blockDim.x) {
        const float4* kp = (const float4*)(k + (size_t)i * 8);
        const float4* vp = (const float4*)(v + (size_t)i * 8);
        float4 k0 = kp[0], k1 = kp[1];
        float4 v0 = vp[0], v1 = vp[1];
        uint4 ko, vo;
        ko.x = pack_h2(k0.x, k0.y); ko.y = pack_h2(k0.z, k0.w);
        ko.z = pack_h2(k1.x, k1.y); ko.w = pack_h2(k1.z, k1.w);
        vo.x = pack_h2(v0.x, v0.y); vo.y = pack_h2(v0.z, v0.w);
        vo.z = pack_h2(v1.x, v1.y); vo.w = pack_h2(v1.z, v1.w);
        *(uint4*)(g_kh + (size_t)i * 8) = ko;
        *(uint4*)(g_vh + (size_t)i * 8) = vo;
    }
}

// ---------------- main kernel ----------------
__global__ __launch_bounds__(NT, 1)
void fa_f16_r17_kernel(const float* __restrict__ q, const int* __restrict__ cu,
                       float* __restrict__ out, int B, int Tm1)
{
    extern __shared__ __half smem[];
    const uint32_t sbase = smem_u32(smem);

    // ---- flattened work mapping: longest first ----
    const int head = blockIdx.x;
    int w = blockIdx.y;
    int seq = -1, q0 = 0, s0 = 0, L = 0;
    for (int si = 0; si < B; si++) {
        const int a = cu[si], b = cu[si + 1];
        const int nq = (b - a + TQ - 1) / TQ;
        if (w < nq) { seq = si; s0 = a; L = b - a; q0 = (nq - 1 - w) * TQ; break; }
        w -= nq;
    }
    if (seq < 0) return;

    const int kvh  = head >> 2;
    const int tid  = threadIdx.x;
    const int wid  = tid >> 5;
    const int lane = tid & 31;
    const int g    = lane >> 2;
    const int tig  = lane & 3;
    const int lm   = lane >> 3;
    const int lr   = lane & 7;

    const int pr = wid & 3;          // row group (0..3): rows [pr*32, pr*32+32)
    const int hw = wid >> 2;         // 0/1: token-half for QK, dim-half for PV

    const int qg_max = min(q0 + TQ - 1, L - 1);
    const int nst    = qg_max / TKS + 1;

    const __half* khead = g_kh + kvh * DH;
    const __half* vhead = g_vh + kvh * DH;

    auto issue_stage = [&](int t, int st) {
        const int k0 = t * TKS;
        const uint32_t stb = sbase + (uint32_t)(st * STAGE_BYTES);
        #pragma unroll
        for (int it = 0; it < 16; it++) {
            const int c   = tid + it * NT;
            const int kvs = c >> 11;
            const int r   = (c >> 4) & 127;
            const int c16 = c & 15;
            const int tok = k0 + r;
            const int gtok = min(s0 + tok, Tm1);
            const __half* src = (kvs ? vhead : khead)
                + (size_t)gtok * KSTRIDE + c16 * 8;
            const uint32_t dst = stb +
                (uint32_t)((kvs * K_ST_HALVES + r * PADH + c16 * 8) * 2);
            cp16(dst, src, (tok < L) ? 16u : 0u);
        }
    };

    issue_stage(0, 0); cp_commit();

    const int rbase = q0 + pr * 32;
    const int wrow_min = rbase;
    const int wrow_max = min(rbase + 31, L - 1);

    int rrow[4]; bool rok[4];
    #pragma unroll
    for (int i = 0; i < 4; i++) {
        rrow[i] = rbase + (i >> 1) * 16 + (i & 1) * 8 + g;
        rok[i]  = rrow[i] < L;
    }

    // ---- Q fragments directly from gmem (m16n8k16 A layout), 2 m-tiles ----
    const float scale = 0.08838834764831845f * 1.4426950408889634f; // *log2e
    uint32_t qa[8][2][4];
    {
        const float2 z = make_float2(0.f, 0.f);
        #pragma unroll
        for (int mt = 0; mt < 2; mt++) {
            const float* pA = q + (size_t)(s0 + min(rrow[mt*2],   L-1)) * QSTRIDE + head * DH;
            const float* pB = q + (size_t)(s0 + min(rrow[mt*2+1], L-1)) * QSTRIDE + head * DH;
            const bool okA = rok[mt*2], okB = rok[mt*2+1];
            #pragma unroll
            for (int ks = 0; ks < 8; ks++) {
                const int c = ks * 16 + tig * 2;
                float2 vA0 = okA ? *(const float2*)(pA + c)     : z;
                float2 vB0 = okB ? *(const float2*)(pB + c)     : z;
                float2 vA1 = okA ? *(const float2*)(pA + c + 8) : z;
                float2 vB1 = okB ? *(const float2*)(pB + c + 8) : z;
                qa[ks][mt][0] = pack_h2(vA0.x * scale, vA0.y * scale);
                qa[ks][mt][1] = pack_h2(vB0.x * scale, vB0.y * scale);
                qa[ks][mt][2] = pack_h2(vA1.x * scale, vA1.y * scale);
                qa[ks][mt][3] = pack_h2(vB1.x * scale, vB1.y * scale);
            }
        }
    }

    float o[2][8][4];
    #pragma unroll
    for (int mt = 0; mt < 2; mt++)
        #pragma unroll
        for (int dt = 0; dt < 8; dt++)
            #pragma unroll
            for (int r = 0; r < 4; r++) o[mt][dt][r] = 0.f;
    float lsum[4] = {0.f, 0.f, 0.f, 0.f};

    const uint32_t koff = (uint32_t)((((lm >> 1) * 8 + lr) * PADH + (lm & 1) * 8) * 2);
    const uint32_t vbase_off = (uint32_t)((((lm & 1) * 8 + lr) * PADH
                                + hw * 64 + (lm >> 1) * 8) * 2);
    uint32_t pbase[2];
    #pragma unroll
    for (int mt = 0; mt < 2; mt++)
        pbase[mt] = sbase + P_OFF_B +
            (uint32_t)(((pr * 32 + mt * 16 + (lm & 1) * 8 + lr) * PPADH
                        + (lm >> 1) * 8) * 2);
    uint32_t pwrow[4];
    #pragma unroll
    for (int i = 0; i < 4; i++)
        pwrow[i] = sbase + P_OFF_B +
            (uint32_t)((pr * 32 + (i >> 1) * 16 + (i & 1) * 8 + g) * PPADH * 2);

    for (int t = 0; t < nst; t++) {
        cp_wait0();
        __syncthreads();
        if (t + 1 < nst) { issue_stage(t + 1, (t + 1) & 1); cp_commit(); }

        const uint32_t KstB = sbase + (uint32_t)((t & 1) * STAGE_BYTES);
        const uint32_t VstB = KstB + (uint32_t)(K_ST_HALVES * 2);
        const int k0s = t * TKS;
        const int tb  = k0s + hw * 64;
        const int cap = wrow_max - tb;

        // ---------- QK over token-half, or zero-P ----------
        if (cap >= 0) {
            const uint32_t Kst = KstB + (uint32_t)(hw * 64 * PADH * 2);
            float s[2][8][4];
            #pragma unroll
            for (int mt = 0; mt < 2; mt++)
                #pragma unroll
                for (int nt = 0; nt < 8; nt++)
                    s[mt][nt][0] = s[mt][nt][1] = s[mt][nt][2] = s[mt][nt][3] = 0.f;
            {
                uint32_t br[2][4];
                ldsm4(br[0], Kst + koff);
                #pragma unroll
                for (int st = 0; st < 32; st++) {
                    if (st + 1 < 32) {
                        const int ns = st + 1;
                        ldsm4(br[ns & 1], Kst + koff +
                              (uint32_t)(((ns & 3) * 16 * PADH + (ns >> 2) * 16) * 2));
                    }
                    const int ks = st >> 2, j = st & 3;
                    mma_f16(s[0][2*j],   qa[ks][0], br[st & 1][0], br[st & 1][1]);
                    mma_f16(s[1][2*j],   qa[ks][1], br[st & 1][0], br[st & 1][1]);
                    mma_f16(s[0][2*j+1], qa[ks][0], br[st & 1][2], br[st & 1][3]);
                    mma_f16(s[1][2*j+1], qa[ks][1], br[st & 1][2], br[st & 1][3]);
                }
            }
            const bool nomask = wrow_min >= tb + 63;
            #pragma unroll
            for (int mt = 0; mt < 2; mt++) {
                const int qA = rrow[mt*2], qB = rrow[mt*2+1];
                #pragma unroll
                for (int nt = 0; nt < 8; nt++) {
                    float p0, p1, p2, p3;
                    if (nomask) {
                        p0 = exp2f_fast(s[mt][nt][0]);
                        p1 = exp2f_fast(s[mt][nt][1]);
                        p2 = exp2f_fast(s[mt][nt][2]);
                        p3 = exp2f_fast(s[mt][nt][3]);
                    } else {
                        const int cb = tb + nt * 8 + tig * 2;
                        p0 = (cb     <= qA) ? exp2f_fast(s[mt][nt][0]) : 0.f;
                        p1 = (cb + 1 <= qA) ? exp2f_fast(s[mt][nt][1]) : 0.f;
                        p2 = (cb     <= qB) ? exp2f_fast(s[mt][nt][2]) : 0.f;
                        p3 = (cb + 1 <= qB) ? exp2f_fast(s[mt][nt][3]) : 0.f;
                    }
                    lsum[mt*2]   += p0 + p1;
                    lsum[mt*2+1] += p2 + p3;
                    const uint32_t coff = (uint32_t)((hw * 64 + nt * 8 + tig * 2) * 2);
                    sts32(pwrow[mt*2]   + coff, pack_h2(p0, p1));
                    sts32(pwrow[mt*2+1] + coff, pack_h2(p2, p3));
                }
            }
        } else {
            #pragma unroll
            for (int i = 0; i < 4; i++)
                #pragma unroll
                for (int nt = 0; nt < 8; nt++)
                    sts32(pwrow[i] + (uint32_t)((hw * 64 + nt * 8 + tig * 2) * 2), 0u);
        }
        __syncthreads();   // P complete for the pair

        // ---------- PV over dim-half, all visible tokens ----------
        if (wrow_max >= k0s) {
            const int kkmax = (wrow_max >= k0s + TK) ? 8 : 4;
            uint32_t pf[2][2][4], vf[2][4][4];
            #pragma unroll
            for (int mt = 0; mt < 2; mt++) ldsm4(pf[0][mt], pbase[mt]);
            #pragma unroll
            for (int dt = 0; dt < 4; dt++)
                ldsm4t(vf[0][dt], VstB + vbase_off + (uint32_t)((dt * 16) * 2));
            for (int kk = 0; kk < kkmax; kk++) {
                const int cur = kk & 1;
                if (kk + 1 < kkmax) {
                    const int nk = kk + 1;
                    #pragma unroll
                    for (int mt = 0; mt < 2; mt++)
                        ldsm4(pf[nk & 1][mt], pbase[mt] + (uint32_t)(nk * 32));
                    #pragma unroll
                    for (int dt = 0; dt < 4; dt++)
                        ldsm4t(vf[nk & 1][dt], VstB + vbase_off +
                               (uint32_t)((nk * 16 * PADH + dt * 16) * 2));
                }
                #pragma unroll
                for (int mt = 0; mt < 2; mt++)
                    #pragma unroll
                    for (int dt = 0; dt < 4; dt++) {
                        mma_f16(o[mt][2*dt],   pf[cur][mt], vf[cur][dt][0], vf[cur][dt][1]);
                        mma_f16(o[mt][2*dt+1], pf[cur][mt], vf[cur][dt][2], vf[cur][dt][3]);
                    }
            }
        }
    }

    // ---- epilogue: quad-reduce l, pair-exchange via smem, store d-half ----
    #pragma unroll
    for (int i = 0; i < 4; i++) {
        lsum[i] += __shfl_xor_sync(0xffffffffu, lsum[i], 1);
        lsum[i] += __shfl_xor_sync(0xffffffffu, lsum[i], 2);
    }
    float* Lb = (float*)((char*)smem + L_OFF_B);
    if (tig == 0) {
        #pragma unroll
        for (int i = 0; i < 4; i++) {
            const int lrow = pr * 32 + (i >> 1) * 16 + (i & 1) * 8 + g;
            Lb[hw * 128 + lrow] = lsum[i];
        }
    }
    __syncthreads();
    float inv[4];
    #pragma unroll
    for (int i = 0; i < 4; i++) {
        const int lrow = pr * 32 + (i >> 1) * 16 + (i & 1) * 8 + g;
        inv[i] = 1.0f / (lsum[i] + Lb[(1 - hw) * 128 + lrow]);
    }

    #pragma unroll
    for (int mt = 0; mt < 2; mt++) {
        float* oA = out + (size_t)(s0 + rrow[mt*2])   * QSTRIDE + head * DH;
        float* oB = out + (size_t)(s0 + rrow[mt*2+1]) * QSTRIDE + head * DH;
        const bool okA = rok[mt*2], okB = rok[mt*2+1];
        const float iA = inv[mt*2], iB = inv[mt*2+1];
        #pragma unroll
        for (int dt = 0; dt < 8; dt++) {
            const int c = hw * 64 + dt * 8 + tig * 2;
            if (okA) *(float2*)(oA + c) =
                make_float2(o[mt][dt][0] * iA, o[mt][dt][1] * iA);
            if (okB) *(float2*)(oB + c) =
                make_float2(o[mt][dt][2] * iB, o[mt][dt][3] * iB);
        }
    }
}

extern "C" void kernel_launch(void* const* d_in, const int* in_sizes, int n_in,
                              void* d_out, int out_size)
{
    const float* q  = (const float*)d_in[0];
    const float* k  = (const float*)d_in[1];
    const float* v  = (const float*)d_in[2];
    const int*   cu = (const int*)d_in[3];

    const int T = in_sizes[0] / QSTRIDE;
    const int B = in_sizes[3] - 1;

    const int n8 = T * KSTRIDE / 8;
    cvt_kv_kernel<<<592, 256>>>(k, v, n8);

    const int wub = (T + TQ - 1) / TQ + B;

    cudaFuncSetAttribute(fa_f16_r17_kernel,
                         cudaFuncAttributeMaxDynamicSharedMemorySize, SMEM_BYTES);

    dim3 grid(32, wub);
    fa_f16_r17_kernel<<<grid, NT, SMEM_BYTES>>>(q, cu, (float*)d_out, B, T - 1);
}